// round 1
// baseline (speedup 1.0000x reference)
#include <cuda_runtime.h>

#define BATCH 8192
#define NDIM  1024
#define MDIM  8192
#define MHALF 4096

#define BK 8
#define BM 128
#define BN 128

// Scratch (static device globals: allocation-free per harness rules)
__device__ float g_Wq[(size_t)NDIM * MHALF];   // quantized expanded weights [N][MHALF]
__device__ float g_Wc[(size_t)NDIM * MHALF];   // gathered continuous weights [N][MHALF]
__device__ float g_xq[(size_t)BATCH * NDIM];   // quantized activations
__device__ float g_H [(size_t)BATCH * MDIM];   // hidden = [H_exp | H_cont]
__device__ int   g_amax[2];                    // float bits of absmax(x), absmax(H_exp)

__global__ void reset_kernel() {
    g_amax[0] = 0;
    g_amax[1] = 0;
}

// One warp per 32-element block of flattened W[:, idx].
__global__ void quant_w_kernel(const float* __restrict__ W, const int* __restrict__ idx) {
    int gw   = (blockIdx.x * blockDim.x + threadIdx.x) >> 5;
    int lane = threadIdx.x & 31;
    if (gw >= (NDIM * MHALF) / 32) return;
    int flat = gw * 32 + lane;
    int n = flat >> 12;            // / MHALF
    int j = flat & (MHALF - 1);
    int col = idx[j];
    float w = W[(size_t)n * MDIM + col];

    // block scale = max(|w|) clipped at 1e-8
    float aw = fabsf(w);
    float s = aw;
    #pragma unroll
    for (int o = 16; o; o >>= 1) s = fmaxf(s, __shfl_xor_sync(0xffffffffu, s, o));
    s = fmaxf(s, 1e-8f);

    float nb  = w / s;
    float anb = fabsf(nb);

    // top-2 by |nb|, ties -> lower index (matches jax.lax.top_k stability)
    float v1 = anb; int i1 = lane;
    #pragma unroll
    for (int o = 16; o; o >>= 1) {
        float ov = __shfl_xor_sync(0xffffffffu, v1, o);
        int   oi = __shfl_xor_sync(0xffffffffu, i1, o);
        if (ov > v1 || (ov == v1 && oi < i1)) { v1 = ov; i1 = oi; }
    }
    float m2 = (lane == i1) ? -1.0f : anb;
    float v2 = m2; int i2 = lane;
    #pragma unroll
    for (int o = 16; o; o >>= 1) {
        float ov = __shfl_xor_sync(0xffffffffu, v2, o);
        int   oi = __shfl_xor_sync(0xffffffffu, i2, o);
        if (ov > v2 || (ov == v2 && oi < i2)) { v2 = ov; i2 = oi; }
    }
    bool top = (lane == i1) || (lane == i2);

    float q4  = rintf(nb * 7.0f) / 7.0f;
    float sgn = (nb > 0.0f) ? 1.0f : ((nb < 0.0f) ? -1.0f : 0.0f);
    float q2  = sgn * ((anb > 0.66f) ? 1.0f : (1.0f / 3.0f));
    g_Wq[flat] = (top ? q4 : q2) * s;
}

__global__ void gather_wc_kernel(const float* __restrict__ W, const int* __restrict__ idxc) {
    int t = blockIdx.x * blockDim.x + threadIdx.x;
    if (t >= NDIM * MHALF) return;
    int n = t >> 12;
    int j = t & (MHALF - 1);
    g_Wc[t] = W[(size_t)n * MDIM + idxc[j]];
}

__global__ void absmax_x_kernel(const float4* __restrict__ x4) {
    __shared__ float sm[256];
    const long n4 = (long)BATCH * NDIM / 4;
    float m = 0.0f;
    for (long i = (long)blockIdx.x * blockDim.x + threadIdx.x; i < n4;
         i += (long)gridDim.x * blockDim.x) {
        float4 v = x4[i];
        m = fmaxf(m, fmaxf(fmaxf(fabsf(v.x), fabsf(v.y)), fmaxf(fabsf(v.z), fabsf(v.w))));
    }
    sm[threadIdx.x] = m;
    __syncthreads();
    #pragma unroll
    for (int s = 128; s; s >>= 1) {
        if (threadIdx.x < s) sm[threadIdx.x] = fmaxf(sm[threadIdx.x], sm[threadIdx.x + s]);
        __syncthreads();
    }
    if (threadIdx.x == 0) atomicMax(&g_amax[0], __float_as_int(sm[0]));
}

__global__ void quant_x_kernel(const float* __restrict__ x) {
    int i = blockIdx.x * blockDim.x + threadIdx.x;
    if (i >= BATCH * NDIM) return;
    float mx = fmaxf(__int_as_float(g_amax[0]), 1e-8f);
    float sc = 127.0f / mx;
    float q  = fminf(fmaxf(rintf(x[i] * sc), -128.0f), 127.0f);
    g_xq[i] = q / sc;
}

// C = A @ B for both halves of hidden; fuses absmax(H_exp) into the epilogue.
__global__ void __launch_bounds__(256) gemm_hidden_kernel(const float* __restrict__ x) {
    __shared__ float As[BK][BM];
    __shared__ float Bs[BK][BN];
    __shared__ float sred[256];

    int jT = blockIdx.x, iT = blockIdx.y;
    bool exp_half = jT < (MHALF / BN);
    const float* A  = exp_half ? g_xq : x;
    const float* Bm = exp_half ? g_Wq : g_Wc;
    int jcol = exp_half ? jT * BN : (jT - MHALF / BN) * BN;
    int row0 = iT * BM;

    int tid  = threadIdx.x;
    int lRow = tid >> 1, lK = (tid & 1) * 4;   // A tile load: 128 rows x 8 k
    int bRow = tid >> 5, bCol = (tid & 31) * 4; // B tile load: 8 k x 128 cols
    int ty = tid >> 4, tx = tid & 15;

    float acc[8][8] = {};

    for (int k0 = 0; k0 < NDIM; k0 += BK) {
        float4 av = *(const float4*)&A[(size_t)(row0 + lRow) * NDIM + k0 + lK];
        As[lK + 0][lRow] = av.x; As[lK + 1][lRow] = av.y;
        As[lK + 2][lRow] = av.z; As[lK + 3][lRow] = av.w;

        float4 bv = *(const float4*)&Bm[(size_t)(k0 + bRow) * MHALF + jcol + bCol];
        *(float4*)&Bs[bRow][bCol] = bv;
        __syncthreads();

        #pragma unroll
        for (int kk = 0; kk < BK; kk++) {
            float ra[8], rb[8];
            *(float4*)(ra)     = *(const float4*)&As[kk][ty * 8];
            *(float4*)(ra + 4) = *(const float4*)&As[kk][ty * 8 + 4];
            *(float4*)(rb)     = *(const float4*)&Bs[kk][tx * 8];
            *(float4*)(rb + 4) = *(const float4*)&Bs[kk][tx * 8 + 4];
            #pragma unroll
            for (int i = 0; i < 8; i++)
                #pragma unroll
                for (int j = 0; j < 8; j++)
                    acc[i][j] += ra[i] * rb[j];
        }
        __syncthreads();
    }

    float lmax = 0.0f;
    #pragma unroll
    for (int i = 0; i < 8; i++) {
        size_t orow = (size_t)(row0 + ty * 8 + i) * MDIM + (size_t)jT * BN + tx * 8;
        float4 v0 = make_float4(acc[i][0], acc[i][1], acc[i][2], acc[i][3]);
        float4 v1 = make_float4(acc[i][4], acc[i][5], acc[i][6], acc[i][7]);
        *(float4*)&g_H[orow]     = v0;
        *(float4*)&g_H[orow + 4] = v1;
        #pragma unroll
        for (int j = 0; j < 8; j++) lmax = fmaxf(lmax, fabsf(acc[i][j]));
    }

    if (exp_half) {
        sred[tid] = lmax;
        __syncthreads();
        #pragma unroll
        for (int s = 128; s; s >>= 1) {
            if (tid < s) sred[tid] = fmaxf(sred[tid], sred[tid + s]);
            __syncthreads();
        }
        if (tid == 0) atomicMax(&g_amax[1], __float_as_int(sred[0]));
    }
}

// out = relu([q(H_exp)|H_cont] @ [Wq;Wc]^T + b); quantization of H_exp fused into A load.
__global__ void __launch_bounds__(256) gemm_out_kernel(const float* __restrict__ bias,
                                                       float* __restrict__ out) {
    __shared__ float As[BK][BM];
    __shared__ float Bs[BK][BN];

    int nT = blockIdx.x, iT = blockIdx.y;
    int row0 = iT * BM, n0 = nT * BN;

    int tid  = threadIdx.x;
    int lRow = tid >> 1, lK = (tid & 1) * 4;
    int ty = tid >> 4, tx = tid & 15;

    float mh     = fmaxf(__int_as_float(g_amax[1]), 1e-8f);
    float sh     = 127.0f / mh;
    float inv_sh = 1.0f / sh;

    float acc[8][8] = {};

    for (int k0 = 0; k0 < MDIM; k0 += BK) {
        bool expk = (k0 < MHALF);

        float4 av = *(const float4*)&g_H[(size_t)(row0 + lRow) * MDIM + k0 + lK];
        if (expk) {
            av.x = fminf(fmaxf(rintf(av.x * sh), -128.0f), 127.0f) * inv_sh;
            av.y = fminf(fmaxf(rintf(av.y * sh), -128.0f), 127.0f) * inv_sh;
            av.z = fminf(fmaxf(rintf(av.z * sh), -128.0f), 127.0f) * inv_sh;
            av.w = fminf(fmaxf(rintf(av.w * sh), -128.0f), 127.0f) * inv_sh;
        }
        As[lK + 0][lRow] = av.x; As[lK + 1][lRow] = av.y;
        As[lK + 2][lRow] = av.z; As[lK + 3][lRow] = av.w;

        // B[k][n] = Wq[n][k] (k<MHALF) else Wc[n][k-MHALF]; transposed stage into smem
        const float* Wrow = expk ? &g_Wq[(size_t)(n0 + lRow) * MHALF + k0]
                                 : &g_Wc[(size_t)(n0 + lRow) * MHALF + (k0 - MHALF)];
        float4 wv = *(const float4*)&Wrow[lK];
        Bs[lK + 0][lRow] = wv.x; Bs[lK + 1][lRow] = wv.y;
        Bs[lK + 2][lRow] = wv.z; Bs[lK + 3][lRow] = wv.w;
        __syncthreads();

        #pragma unroll
        for (int kk = 0; kk < BK; kk++) {
            float ra[8], rb[8];
            *(float4*)(ra)     = *(const float4*)&As[kk][ty * 8];
            *(float4*)(ra + 4) = *(const float4*)&As[kk][ty * 8 + 4];
            *(float4*)(rb)     = *(const float4*)&Bs[kk][tx * 8];
            *(float4*)(rb + 4) = *(const float4*)&Bs[kk][tx * 8 + 4];
            #pragma unroll
            for (int i = 0; i < 8; i++)
                #pragma unroll
                for (int j = 0; j < 8; j++)
                    acc[i][j] += ra[i] * rb[j];
        }
        __syncthreads();
    }

    #pragma unroll
    for (int i = 0; i < 8; i++) {
        int r = row0 + ty * 8 + i;
        #pragma unroll
        for (int j = 0; j < 8; j++) {
            int n = n0 + tx * 8 + j;
            float v = acc[i][j] + bias[n];
            out[(size_t)r * NDIM + n] = fmaxf(v, 0.0f);
        }
    }
}

extern "C" void kernel_launch(void* const* d_in, const int* in_sizes, int n_in,
                              void* d_out, int out_size) {
    const float* x    = (const float*)d_in[0];
    const float* W    = (const float*)d_in[1];
    const float* b    = (const float*)d_in[2];
    const int*   idx  = (const int*)d_in[3];
    const int*   idxc = (const int*)d_in[4];
    float* out = (float*)d_out;

    reset_kernel<<<1, 32>>>();
    quant_w_kernel<<<(NDIM * MHALF / 32) / 8, 256>>>(W, idx);
    gather_wc_kernel<<<NDIM * MHALF / 256, 256>>>(W, idxc);
    absmax_x_kernel<<<1024, 256>>>((const float4*)x);
    quant_x_kernel<<<BATCH * NDIM / 256, 256>>>(x);
    gemm_hidden_kernel<<<dim3(MDIM / BN, BATCH / BM), 256>>>(x);
    gemm_out_kernel<<<dim3(NDIM / BN, BATCH / BM), 256>>>(b, out);
}

// round 3
// speedup vs baseline: 2.3147x; 2.3147x over previous
#include <cuda_runtime.h>
#include <cstdint>

#define BATCH 8192
#define NDIM  1024
#define MDIM  8192
#define MHALF 4096

// ---------------- scratch ----------------------------------------------------
__device__ float g_WqT_hi[(size_t)MHALF * NDIM];  // [j][n] hi part of Wq
__device__ float g_WqT_lo[(size_t)MHALF * NDIM];  // [j][n] lo part of Wq
__device__ float g_Wq    [(size_t)NDIM * MHALF];  // raw Wq [n][j]
__device__ float g_W2hi  [(size_t)NDIM * MHALF];  // temp hi, later scaled hi
__device__ float g_W2lo  [(size_t)NDIM * MHALF];  // temp lo, later scaled lo
__device__ float g_WcT   [(size_t)MHALF * NDIM];  // tf32(Wc) [j][n]
__device__ float g_Wc    [(size_t)NDIM * MHALF];  // tf32(Wc) [n][j]
__device__ float g_xq    [(size_t)BATCH * NDIM];  // int-valued quantized x
__device__ float g_xc    [(size_t)BATCH * NDIM];  // tf32(x)
__device__ float g_H     [(size_t)BATCH * MDIM];  // hidden (exp raw->ints, cont tf32)
__device__ int   g_amax[2];

// ---------------- helpers ----------------------------------------------------
__device__ __forceinline__ float to_tf32(float x) {
    float r; asm("cvt.rna.tf32.f32 %0, %1;" : "=f"(r) : "f"(x)); return r;
}
__device__ __forceinline__ uint32_t smem_u32(const void* p) {
    uint32_t a;
    asm("{ .reg .u64 t; cvta.to.shared.u64 t, %1; cvt.u32.u64 %0, t; }" : "=r"(a) : "l"(p));
    return a;
}
__device__ __forceinline__ void cp16(uint32_t d, const float* s) {
    asm volatile("cp.async.cg.shared.global [%0], [%1], 16;" :: "r"(d), "l"(s));
}
__device__ __forceinline__ void cp_commit() {
    asm volatile("cp.async.commit_group;" ::: "memory");
}
template<int N> __device__ __forceinline__ void cp_wait() {
    asm volatile("cp.async.wait_group %0;" :: "n"(N) : "memory");
}
__device__ __forceinline__ void mma8(float* d, const uint32_t* a, uint32_t b0, uint32_t b1) {
    asm volatile(
        "mma.sync.aligned.m16n8k8.row.col.f32.tf32.tf32.f32 "
        "{%0,%1,%2,%3},{%4,%5,%6,%7},{%8,%9},{%0,%1,%2,%3};"
        : "+f"(d[0]), "+f"(d[1]), "+f"(d[2]), "+f"(d[3])
        : "r"(a[0]), "r"(a[1]), "r"(a[2]), "r"(a[3]), "r"(b0), "r"(b1));
}
// swizzled smem word index for a [rows][32 floats] tile (16B-chunk xor swizzle)
__device__ __forceinline__ int sidx(int r, int k) {
    return r * 32 + (((k >> 2) ^ (r & 7)) << 2) + (k & 3);
}

// ---------------- prep kernels ----------------------------------------------
__global__ void reset_kernel() { g_amax[0] = 0; g_amax[1] = 0; }

__global__ void quant_w_kernel(const float* __restrict__ W, const int* __restrict__ idx) {
    int gw   = (blockIdx.x * blockDim.x + threadIdx.x) >> 5;
    int lane = threadIdx.x & 31;
    if (gw >= (NDIM * MHALF) / 32) return;
    int flat = gw * 32 + lane;
    int n = flat >> 12;
    int j = flat & (MHALF - 1);
    float w = W[(size_t)n * MDIM + idx[j]];

    float s = fabsf(w);
    #pragma unroll
    for (int o = 16; o; o >>= 1) s = fmaxf(s, __shfl_xor_sync(0xffffffffu, s, o));
    s = fmaxf(s, 1e-8f);

    float nb  = w / s;
    float anb = fabsf(nb);

    float v1 = anb; int i1 = lane;
    #pragma unroll
    for (int o = 16; o; o >>= 1) {
        float ov = __shfl_xor_sync(0xffffffffu, v1, o);
        int   oi = __shfl_xor_sync(0xffffffffu, i1, o);
        if (ov > v1 || (ov == v1 && oi < i1)) { v1 = ov; i1 = oi; }
    }
    float m2 = (lane == i1) ? -1.0f : anb;
    float v2 = m2; int i2 = lane;
    #pragma unroll
    for (int o = 16; o; o >>= 1) {
        float ov = __shfl_xor_sync(0xffffffffu, v2, o);
        int   oi = __shfl_xor_sync(0xffffffffu, i2, o);
        if (ov > v2 || (ov == v2 && oi < i2)) { v2 = ov; i2 = oi; }
    }
    bool top = (lane == i1) || (lane == i2);

    float q4  = rintf(nb * 7.0f) / 7.0f;
    float sgn = (nb > 0.0f) ? 1.0f : ((nb < 0.0f) ? -1.0f : 0.0f);
    float q2  = sgn * ((anb > 0.66f) ? 1.0f : (1.0f / 3.0f));
    float val = (top ? q4 : q2) * s;

    float hi = to_tf32(val);
    float lo = to_tf32(val - hi);
    g_Wq  [flat] = val;   // raw, re-split with scale later
    g_W2hi[flat] = hi;    // temp (transposed next)
    g_W2lo[flat] = lo;    // temp (transposed next)
}

__global__ void gather_wc_kernel(const float* __restrict__ W, const int* __restrict__ idxc) {
    int t = blockIdx.x * blockDim.x + threadIdx.x;
    if (t >= NDIM * MHALF) return;
    int n = t >> 12;
    int j = t & (MHALF - 1);
    g_Wc[t] = to_tf32(W[(size_t)n * MDIM + idxc[j]]);
}

// transpose [NDIM][MHALF] -> [MHALF][NDIM] for 3 matrices (hi, lo, Wc)
__global__ void transpose_kernel() {
    __shared__ float t[32][33];
    int z = blockIdx.z;
    const float* src = (z == 0) ? g_W2hi : (z == 1) ? g_W2lo : g_Wc;
    float*       dst = (z == 0) ? g_WqT_hi : (z == 1) ? g_WqT_lo : g_WcT;
    int j0 = blockIdx.x * 32, n0 = blockIdx.y * 32;
    int tx = threadIdx.x, ty = threadIdx.y;
    #pragma unroll
    for (int s = 0; s < 32; s += 8)
        t[ty + s][tx] = src[(size_t)(n0 + ty + s) * MHALF + j0 + tx];
    __syncthreads();
    #pragma unroll
    for (int s = 0; s < 32; s += 8)
        dst[(size_t)(j0 + ty + s) * NDIM + n0 + tx] = t[tx][ty + s];
}

__global__ void absmax_x_kernel(const float4* __restrict__ x4) {
    __shared__ float sm[256];
    const long n4 = (long)BATCH * NDIM / 4;
    float m = 0.0f;
    for (long i = (long)blockIdx.x * blockDim.x + threadIdx.x; i < n4;
         i += (long)gridDim.x * blockDim.x) {
        float4 v = x4[i];
        m = fmaxf(m, fmaxf(fmaxf(fabsf(v.x), fabsf(v.y)), fmaxf(fabsf(v.z), fabsf(v.w))));
    }
    sm[threadIdx.x] = m;
    __syncthreads();
    #pragma unroll
    for (int s = 128; s; s >>= 1) {
        if (threadIdx.x < s) sm[threadIdx.x] = fmaxf(sm[threadIdx.x], sm[threadIdx.x + s]);
        __syncthreads();
    }
    if (threadIdx.x == 0) atomicMax(&g_amax[0], __float_as_int(sm[0]));
}

__global__ void quant_x_kernel(const float* __restrict__ x) {
    int i = blockIdx.x * blockDim.x + threadIdx.x;
    if (i >= BATCH * NDIM) return;
    float sc = 127.0f / fmaxf(__int_as_float(g_amax[0]), 1e-8f);
    float v = x[i];
    g_xq[i] = fminf(fmaxf(rintf(v * sc), -128.0f), 127.0f);  // integer-valued
    g_xc[i] = to_tf32(v);
}

// after GEMM1: W2hi/lo = split( (amax_h/127) * Wq )
__global__ void scale_w2_kernel() {
    int i = blockIdx.x * blockDim.x + threadIdx.x;
    if (i >= NDIM * MHALF) return;
    float finv = fmaxf(__int_as_float(g_amax[1]), 1e-8f) * (1.0f / 127.0f);
    float v = g_Wq[i] * finv;
    float hi = to_tf32(v);
    g_W2hi[i] = hi;
    g_W2lo[i] = to_tf32(v - hi);
}

// quantize H[:, 0:MHALF] in place to integer-valued floats
__global__ void quant_h_kernel() {
    int t = blockIdx.x * blockDim.x + threadIdx.x;
    if (t >= BATCH * MHALF / 4) return;
    int row = t >> 10;            // / (MHALF/4)
    int c4  = (t & 1023) * 4;
    float sh = 127.0f / fmaxf(__int_as_float(g_amax[1]), 1e-8f);
    float4* p = (float4*)&g_H[(size_t)row * MDIM + c4];
    float4 v = *p;
    v.x = fminf(fmaxf(rintf(v.x * sh), -128.0f), 127.0f);
    v.y = fminf(fmaxf(rintf(v.y * sh), -128.0f), 127.0f);
    v.z = fminf(fmaxf(rintf(v.z * sh), -128.0f), 127.0f);
    v.w = fminf(fmaxf(rintf(v.w * sh), -128.0f), 127.0f);
    *p = v;
}

// ---------------- pipelined warp-MMA GEMM ------------------------------------
// C[128,128] per CTA; A[M,K] row-major, B[N,K] row-major (contraction over K).
// mode 0: hidden (exp: A=xq ints, B=WqT hi/lo split; cont: A=xc, B=WcT)
// mode 1: out    (k<4096: A=Hq ints, B=W2hi/lo; k>=4096: A=Hcont, B=Wc) +bias+relu
#define STG_FLOATS 12288   // 48KB per stage: A(4096) B0(4096) B1(4096)

__global__ void __launch_bounds__(256, 1) gemm_mma_kernel(float* __restrict__ outp,
                                                          const float* __restrict__ biasp,
                                                          int mode) {
    extern __shared__ float smem[];
    const int tid = threadIdx.x, wid = tid >> 5, lane = tid & 31;
    const int g = lane >> 2, tig = lane & 3;
    const int wm0 = (wid & 1) * 64, wn0 = (wid >> 1) * 32;
    const int bx = blockIdx.x, by = blockIdx.y;
    const int row0 = by * 128;

    int NCH, lda, ldb, ldc, ccol0;
    const float *Abase, *B0base = nullptr, *B1base = nullptr;
    float* Cptr;
    bool expmode = false;
    if (mode == 0) {
        NCH = NDIM / 32; lda = NDIM; ldb = NDIM; ldc = MDIM;
        expmode = bx < (MHALF / 128);
        int n0 = expmode ? bx * 128 : (bx - MHALF / 128) * 128;
        Abase  = (expmode ? g_xq : g_xc) + (size_t)row0 * NDIM;
        B0base = (expmode ? g_WqT_hi : g_WcT) + (size_t)n0 * NDIM;
        B1base = g_WqT_lo + (size_t)n0 * NDIM;
        Cptr  = g_H;
        ccol0 = expmode ? n0 : MHALF + n0;
    } else {
        NCH = MDIM / 32; lda = MDIM; ldb = MHALF; ldc = NDIM;
        int n0 = bx * 128;
        Abase  = g_H + (size_t)row0 * MDIM;
        B0base = g_W2hi + (size_t)n0 * MHALF;   // phase-1 (k<MHALF)
        B1base = g_W2lo + (size_t)n0 * MHALF;
        Cptr  = outp;
        ccol0 = n0;
        // phase-2 base resolved inline
    }
    const float* Wc2base = g_Wc + (size_t)(bx * 128) * MHALF;  // mode1 phase2

    const uint32_t sbase = smem_u32(smem);

    // -------- issue one chunk's cp.asyncs --------
    auto issue = [&](int c) {
        const int k0 = c * 32;
        const uint32_t st = sbase + (uint32_t)(c & 3) * STG_FLOATS * 4;
        bool split;
        const float *Bs0, *Bs1 = nullptr;
        if (mode == 0) {
            split = expmode;
            Bs0 = B0base + k0;
            if (split) Bs1 = B1base + k0;
        } else {
            split = (k0 < MHALF);
            if (split) { Bs0 = B0base + k0; Bs1 = B1base + k0; }
            else       { Bs0 = Wc2base + (k0 - MHALF); }
        }
        const float* As = Abase + k0;
        #pragma unroll
        for (int p = 0; p < 4; p++) {
            int l = tid + p * 256;
            int r = l >> 3, cc = l & 7;
            uint32_t doff = (uint32_t)(r * 32 + ((cc ^ (r & 7)) << 2)) * 4;
            cp16(st + doff,           As  + (size_t)r * lda + cc * 4);
            cp16(st + 16384 + doff,   Bs0 + (size_t)r * ldb + cc * 4);
            if (split)
                cp16(st + 32768 + doff, Bs1 + (size_t)r * ldb + cc * 4);
        }
        cp_commit();
    };

    issue(0); issue(1); issue(2);

    float acc[4][4][4] = {};

    for (int c = 0; c < NCH; c++) {
        cp_wait<2>();
        __syncthreads();
        if (c + 3 < NCH) issue(c + 3); else cp_commit();

        const float* sA  = smem + (c & 3) * STG_FLOATS;
        const float* sB0 = sA + 4096;
        const float* sB1 = sA + 8192;
        const bool dosplit = (mode == 0) ? expmode : (c < MHALF / 32);

        #pragma unroll
        for (int ks = 0; ks < 4; ks++) {
            const int k = ks * 8 + tig;
            uint32_t a[4][4];
            #pragma unroll
            for (int i = 0; i < 4; i++) {
                int r = wm0 + i * 16 + g;
                a[i][0] = __float_as_uint(sA[sidx(r,     k)]);
                a[i][1] = __float_as_uint(sA[sidx(r + 8, k)]);
                a[i][2] = __float_as_uint(sA[sidx(r,     k + 4)]);
                a[i][3] = __float_as_uint(sA[sidx(r + 8, k + 4)]);
            }
            #pragma unroll
            for (int j = 0; j < 4; j++) {
                int n = wn0 + j * 8 + g;
                uint32_t bh0 = __float_as_uint(sB0[sidx(n, k)]);
                uint32_t bh1 = __float_as_uint(sB0[sidx(n, k + 4)]);
                #pragma unroll
                for (int i = 0; i < 4; i++) mma8(acc[i][j], a[i], bh0, bh1);
                if (dosplit) {
                    uint32_t bl0 = __float_as_uint(sB1[sidx(n, k)]);
                    uint32_t bl1 = __float_as_uint(sB1[sidx(n, k + 4)]);
                    #pragma unroll
                    for (int i = 0; i < 4; i++) mma8(acc[i][j], a[i], bl0, bl1);
                }
            }
        }
        __syncthreads();
    }

    // -------- epilogue --------
    float lmax = 0.0f;
    float inv = 1.0f;
    if (mode == 0 && expmode)
        inv = fmaxf(__int_as_float(g_amax[0]), 1e-8f) * (1.0f / 127.0f);

    #pragma unroll
    for (int i = 0; i < 4; i++) {
        #pragma unroll
        for (int j = 0; j < 4; j++) {
            int r   = row0 + wm0 + i * 16 + g;
            int col = ccol0 + wn0 + j * 8 + tig * 2;
            float v0 = acc[i][j][0] * inv, v1 = acc[i][j][1] * inv;
            float v2 = acc[i][j][2] * inv, v3 = acc[i][j][3] * inv;
            if (mode == 0) {
                if (expmode) {
                    lmax = fmaxf(lmax, fmaxf(fmaxf(fabsf(v0), fabsf(v1)),
                                             fmaxf(fabsf(v2), fabsf(v3))));
                } else {
                    v0 = to_tf32(v0); v1 = to_tf32(v1);
                    v2 = to_tf32(v2); v3 = to_tf32(v3);
                }
            } else {
                float b0 = biasp[col], b1 = biasp[col + 1];
                v0 = fmaxf(v0 + b0, 0.0f); v1 = fmaxf(v1 + b1, 0.0f);
                v2 = fmaxf(v2 + b0, 0.0f); v3 = fmaxf(v3 + b1, 0.0f);
            }
            *(float2*)&Cptr[(size_t)r * ldc + col]       = make_float2(v0, v1);
            *(float2*)&Cptr[(size_t)(r + 8) * ldc + col] = make_float2(v2, v3);
        }
    }

    if (mode == 0 && expmode) {
        __syncthreads();
        smem[tid] = lmax;
        __syncthreads();
        #pragma unroll
        for (int s = 128; s; s >>= 1) {
            if (tid < s) smem[tid] = fmaxf(smem[tid], smem[tid + s]);
            __syncthreads();
        }
        if (tid == 0) atomicMax(&g_amax[1], __float_as_int(smem[0]));
    }
}

// ---------------- launcher ---------------------------------------------------
extern "C" void kernel_launch(void* const* d_in, const int* in_sizes, int n_in,
                              void* d_out, int out_size) {
    const float* x    = (const float*)d_in[0];
    const float* W    = (const float*)d_in[1];
    const float* b    = (const float*)d_in[2];
    const int*   idx  = (const int*)d_in[3];
    const int*   idxc = (const int*)d_in[4];
    float* out = (float*)d_out;

    const int SMEM = 4 * STG_FLOATS * 4;  // 192KB
    cudaFuncSetAttribute(gemm_mma_kernel, cudaFuncAttributeMaxDynamicSharedMemorySize, SMEM);

    reset_kernel<<<1, 32>>>();
    quant_w_kernel<<<(NDIM * MHALF / 32) / 8, 256>>>(W, idx);
    gather_wc_kernel<<<NDIM * MHALF / 256, 256>>>(W, idxc);
    transpose_kernel<<<dim3(MHALF / 32, NDIM / 32, 3), dim3(32, 8)>>>();
    absmax_x_kernel<<<1024, 256>>>((const float4*)x);
    quant_x_kernel<<<BATCH * NDIM / 256, 256>>>(x);

    gemm_mma_kernel<<<dim3(MDIM / 128, BATCH / 128), 256, SMEM>>>(nullptr, nullptr, 0);

    scale_w2_kernel<<<NDIM * MHALF / 256, 256>>>();
    quant_h_kernel<<<(BATCH * MHALF / 4) / 256, 256>>>();

    gemm_mma_kernel<<<dim3(NDIM / 128, BATCH / 128), 256, SMEM>>>(out, b, 1);
}

// round 4
// speedup vs baseline: 3.8703x; 1.6720x over previous
#include <cuda_runtime.h>
#include <cuda_fp16.h>
#include <cuda_bf16.h>
#include <cstdint>

#define BATCH 8192
#define NDIM  1024
#define MDIM  8192
#define MHALF 4096

#define NSTG      4
#define STG_BYTES 49152   // 48KB per stage

// ---------------- scratch ----------------------------------------------------
__device__ float         g_Wq     [(size_t)NDIM * MHALF];   // raw quantized weights [n][j]
__device__ __half        g_WqThi16[(size_t)MHALF * NDIM];   // fp16 hi of 2048*Wq, [j][n]
__device__ __half        g_WqTlo16[(size_t)MHALF * NDIM];   // fp16 lo of 2048*Wq, [j][n]
__device__ float         g_WcT    [(size_t)MHALF * NDIM];   // tf32(Wc) [j][n]
__device__ float         g_Wc     [(size_t)NDIM * MHALF];   // tf32(Wc) [n][j]
__device__ __nv_bfloat16 g_W2hi16 [(size_t)NDIM * MHALF];   // bf16 hi of (amax_h/127)*Wq
__device__ __nv_bfloat16 g_W2lo16 [(size_t)NDIM * MHALF];   // bf16 lo
__device__ __half        g_xq16   [(size_t)BATCH * NDIM];   // int-valued quantized x (fp16)
__device__ float         g_xc     [(size_t)BATCH * NDIM];   // tf32(x)
__device__ float         g_H      [(size_t)BATCH * MDIM];   // hidden (exp raw fp32 | cont tf32)
__device__ __nv_bfloat16 g_Hq16   [(size_t)BATCH * MHALF];  // int-valued quantized H_exp (bf16)
__device__ int           g_amax[2];

// ---------------- helpers ----------------------------------------------------
__device__ __forceinline__ float to_tf32(float x) {
    float r; asm("cvt.rna.tf32.f32 %0, %1;" : "=f"(r) : "f"(x)); return r;
}
__device__ __forceinline__ uint32_t smem_u32(const void* p) {
    uint32_t a;
    asm("{ .reg .u64 t; cvta.to.shared.u64 t, %1; cvt.u32.u64 %0, t; }" : "=r"(a) : "l"(p));
    return a;
}
__device__ __forceinline__ void cp16(uint32_t d, const void* s) {
    asm volatile("cp.async.cg.shared.global [%0], [%1], 16;" :: "r"(d), "l"(s));
}
__device__ __forceinline__ void cp_commit() {
    asm volatile("cp.async.commit_group;" ::: "memory");
}
template<int N> __device__ __forceinline__ void cp_wait() {
    asm volatile("cp.async.wait_group %0;" :: "n"(N) : "memory");
}
__device__ __forceinline__ void mma_tf32(float* d, const uint32_t* a, uint32_t b0, uint32_t b1) {
    asm volatile(
        "mma.sync.aligned.m16n8k8.row.col.f32.tf32.tf32.f32 "
        "{%0,%1,%2,%3},{%4,%5,%6,%7},{%8,%9},{%0,%1,%2,%3};"
        : "+f"(d[0]), "+f"(d[1]), "+f"(d[2]), "+f"(d[3])
        : "r"(a[0]), "r"(a[1]), "r"(a[2]), "r"(a[3]), "r"(b0), "r"(b1));
}
__device__ __forceinline__ void mma_f16(float* d, const uint32_t* a, uint32_t b0, uint32_t b1) {
    asm volatile(
        "mma.sync.aligned.m16n8k16.row.col.f32.f16.f16.f32 "
        "{%0,%1,%2,%3},{%4,%5,%6,%7},{%8,%9},{%0,%1,%2,%3};"
        : "+f"(d[0]), "+f"(d[1]), "+f"(d[2]), "+f"(d[3])
        : "r"(a[0]), "r"(a[1]), "r"(a[2]), "r"(a[3]), "r"(b0), "r"(b1));
}
__device__ __forceinline__ void mma_bf16(float* d, const uint32_t* a, uint32_t b0, uint32_t b1) {
    asm volatile(
        "mma.sync.aligned.m16n8k16.row.col.f32.bf16.bf16.f32 "
        "{%0,%1,%2,%3},{%4,%5,%6,%7},{%8,%9},{%0,%1,%2,%3};"
        : "+f"(d[0]), "+f"(d[1]), "+f"(d[2]), "+f"(d[3])
        : "r"(a[0]), "r"(a[1]), "r"(a[2]), "r"(a[3]), "r"(b0), "r"(b1));
}
// tf32 tile word index: [rows][32 floats], 16B-granule xor swizzle
__device__ __forceinline__ int sidx(int r, int k) {
    return r * 32 + (((k >> 2) ^ (r & 7)) << 2) + (k & 3);
}
// 16-bit tile byte offset: [rows][128B = 64 halves], granule swizzle. kb = byte col
__device__ __forceinline__ int off16(int r, int kb) {
    return r * 128 + ((((kb >> 4) ^ (r & 7)) << 4) | (kb & 15));
}
__device__ __forceinline__ uint32_t lds32(const char* p) {
    return *(const uint32_t*)p;
}

// ---------------- prep kernels ----------------------------------------------
__global__ void reset_kernel() { g_amax[0] = 0; g_amax[1] = 0; }

__global__ void quant_w_kernel(const float* __restrict__ W, const int* __restrict__ idx) {
    int gw   = (blockIdx.x * blockDim.x + threadIdx.x) >> 5;
    int lane = threadIdx.x & 31;
    if (gw >= (NDIM * MHALF) / 32) return;
    int flat = gw * 32 + lane;
    int n = flat >> 12;
    int j = flat & (MHALF - 1);
    float w = W[(size_t)n * MDIM + idx[j]];

    float s = fabsf(w);
    #pragma unroll
    for (int o = 16; o; o >>= 1) s = fmaxf(s, __shfl_xor_sync(0xffffffffu, s, o));
    s = fmaxf(s, 1e-8f);

    float nb  = w / s;
    float anb = fabsf(nb);

    float v1 = anb; int i1 = lane;
    #pragma unroll
    for (int o = 16; o; o >>= 1) {
        float ov = __shfl_xor_sync(0xffffffffu, v1, o);
        int   oi = __shfl_xor_sync(0xffffffffu, i1, o);
        if (ov > v1 || (ov == v1 && oi < i1)) { v1 = ov; i1 = oi; }
    }
    float m2 = (lane == i1) ? -1.0f : anb;
    float v2 = m2; int i2 = lane;
    #pragma unroll
    for (int o = 16; o; o >>= 1) {
        float ov = __shfl_xor_sync(0xffffffffu, v2, o);
        int   oi = __shfl_xor_sync(0xffffffffu, i2, o);
        if (ov > v2 || (ov == v2 && oi < i2)) { v2 = ov; i2 = oi; }
    }
    bool top = (lane == i1) || (lane == i2);

    float q4  = rintf(nb * 7.0f) / 7.0f;
    float sgn = (nb > 0.0f) ? 1.0f : ((nb < 0.0f) ? -1.0f : 0.0f);
    float q2  = sgn * ((anb > 0.66f) ? 1.0f : (1.0f / 3.0f));
    g_Wq[flat] = (top ? q4 : q2) * s;
}

__global__ void gather_wc_kernel(const float* __restrict__ W, const int* __restrict__ idxc) {
    int t = blockIdx.x * blockDim.x + threadIdx.x;
    if (t >= NDIM * MHALF) return;
    int n = t >> 12;
    int j = t & (MHALF - 1);
    g_Wc[t] = to_tf32(W[(size_t)n * MDIM + idxc[j]]);
}

// transpose [NDIM][MHALF] -> [MHALF][NDIM]; z=0: Wq -> fp16 hi/lo (x2048); z=1: Wc -> WcT
__global__ void transpose_kernel() {
    __shared__ float t[32][33];
    int z = blockIdx.z;
    const float* src = (z == 0) ? g_Wq : g_Wc;
    int j0 = blockIdx.x * 32, n0 = blockIdx.y * 32;
    int tx = threadIdx.x, ty = threadIdx.y;
    #pragma unroll
    for (int s = 0; s < 32; s += 8)
        t[ty + s][tx] = src[(size_t)(n0 + ty + s) * MHALF + j0 + tx];
    __syncthreads();
    if (z == 0) {
        #pragma unroll
        for (int s = 0; s < 32; s += 8) {
            float v = t[tx][ty + s] * 2048.0f;
            __half h = __float2half_rn(v);
            __half l = __float2half_rn(v - __half2float(h));
            size_t o = (size_t)(j0 + ty + s) * NDIM + n0 + tx;
            g_WqThi16[o] = h;
            g_WqTlo16[o] = l;
        }
    } else {
        #pragma unroll
        for (int s = 0; s < 32; s += 8)
            g_WcT[(size_t)(j0 + ty + s) * NDIM + n0 + tx] = t[tx][ty + s];
    }
}

__global__ void absmax_x_kernel(const float4* __restrict__ x4) {
    __shared__ float sm[256];
    const long n4 = (long)BATCH * NDIM / 4;
    float m = 0.0f;
    for (long i = (long)blockIdx.x * blockDim.x + threadIdx.x; i < n4;
         i += (long)gridDim.x * blockDim.x) {
        float4 v = x4[i];
        m = fmaxf(m, fmaxf(fmaxf(fabsf(v.x), fabsf(v.y)), fmaxf(fabsf(v.z), fabsf(v.w))));
    }
    sm[threadIdx.x] = m;
    __syncthreads();
    #pragma unroll
    for (int s = 128; s; s >>= 1) {
        if (threadIdx.x < s) sm[threadIdx.x] = fmaxf(sm[threadIdx.x], sm[threadIdx.x + s]);
        __syncthreads();
    }
    if (threadIdx.x == 0) atomicMax(&g_amax[0], __float_as_int(sm[0]));
}

__global__ void quant_x_kernel(const float* __restrict__ x) {
    int i = blockIdx.x * blockDim.x + threadIdx.x;
    if (i >= BATCH * NDIM) return;
    float sc = 127.0f / fmaxf(__int_as_float(g_amax[0]), 1e-8f);
    float v = x[i];
    g_xq16[i] = __float2half_rn(fminf(fmaxf(rintf(v * sc), -128.0f), 127.0f));
    g_xc[i]   = to_tf32(v);
}

// W2hi/lo (bf16) = split( (amax_h/127) * Wq )
__global__ void scale_w2_kernel() {
    int i = blockIdx.x * blockDim.x + threadIdx.x;
    if (i >= NDIM * MHALF) return;
    float f = fmaxf(__int_as_float(g_amax[1]), 1e-8f) * (1.0f / 127.0f);
    float v = g_Wq[i] * f;
    __nv_bfloat16 h = __float2bfloat16_rn(v);
    g_W2hi16[i] = h;
    g_W2lo16[i] = __float2bfloat16_rn(v - __bfloat162float(h));
}

// quantize H[:, 0:MHALF] -> integer-valued bf16 in g_Hq16
__global__ void quant_h_kernel() {
    int t = blockIdx.x * blockDim.x + threadIdx.x;
    if (t >= BATCH * MHALF / 4) return;
    int row = t >> 10;
    int c4  = (t & 1023) * 4;
    float sh = 127.0f / fmaxf(__int_as_float(g_amax[1]), 1e-8f);
    float4 v = *(const float4*)&g_H[(size_t)row * MDIM + c4];
    __nv_bfloat16 o[4];
    o[0] = __float2bfloat16_rn(fminf(fmaxf(rintf(v.x * sh), -128.0f), 127.0f));
    o[1] = __float2bfloat16_rn(fminf(fmaxf(rintf(v.y * sh), -128.0f), 127.0f));
    o[2] = __float2bfloat16_rn(fminf(fmaxf(rintf(v.z * sh), -128.0f), 127.0f));
    o[3] = __float2bfloat16_rn(fminf(fmaxf(rintf(v.w * sh), -128.0f), 127.0f));
    *(uint2*)&g_Hq16[(size_t)row * MHALF + c4] = *(uint2*)o;
}

// ---------------- GEMM1: hidden = [xq@Wq | x@Wc] -----------------------------
// exp CTAs (bx<32): fp16 2-term split, K-chunk 64.  cont: tf32 single, K-chunk 32.
__global__ void __launch_bounds__(256, 1) gemm1_kernel() {
    extern __shared__ char smem[];
    const int tid = threadIdx.x, wid = tid >> 5, lane = tid & 31;
    const int g = lane >> 2, tig = lane & 3;
    const int wm0 = (wid & 1) * 64, wn0 = (wid >> 1) * 32;
    const int bx = blockIdx.x, row0 = blockIdx.y * 128;
    const bool expm = bx < (MHALF / 128);
    const int n0 = expm ? bx * 128 : (bx - MHALF / 128) * 128;
    const uint32_t sbase = smem_u32(smem);
    const int NCH = expm ? (NDIM / 64) : (NDIM / 32);

    auto issue = [&](int c) {
        const uint32_t st = sbase + (uint32_t)(c & 3) * STG_BYTES;
        if (expm) {
            const int k0 = c * 64;
            const __half* As = g_xq16    + (size_t)row0 * NDIM + k0;
            const __half* Bh = g_WqThi16 + (size_t)n0 * NDIM + k0;
            const __half* Bl = g_WqTlo16 + (size_t)n0 * NDIM + k0;
            #pragma unroll
            for (int p = 0; p < 4; p++) {
                int l = tid + p * 256;
                int r = l >> 3, gc = l & 7;
                uint32_t d = st + (uint32_t)(r * 128 + ((gc ^ (r & 7)) << 4));
                cp16(d,         As + (size_t)r * NDIM + gc * 8);
                cp16(d + 16384, Bh + (size_t)r * NDIM + gc * 8);
                cp16(d + 32768, Bl + (size_t)r * NDIM + gc * 8);
            }
        } else {
            const int k0 = c * 32;
            const float* As = g_xc  + (size_t)row0 * NDIM + k0;
            const float* Bs = g_WcT + (size_t)n0 * NDIM + k0;
            #pragma unroll
            for (int p = 0; p < 4; p++) {
                int l = tid + p * 256;
                int r = l >> 3, gc = l & 7;
                uint32_t d = st + (uint32_t)(r * 128 + ((gc ^ (r & 7)) << 4));
                cp16(d,         As + (size_t)r * NDIM + gc * 4);
                cp16(d + 16384, Bs + (size_t)r * NDIM + gc * 4);
            }
        }
        cp_commit();
    };

    issue(0); issue(1); issue(2);

    float acc[4][4][4] = {};

    for (int c = 0; c < NCH; c++) {
        cp_wait<2>();
        __syncthreads();
        if (c + 3 < NCH) issue(c + 3); else cp_commit();

        const char* sA = smem + (c & 3) * STG_BYTES;
        if (expm) {
            const char* sBh = sA + 16384;
            const char* sBl = sA + 32768;
            #pragma unroll
            for (int s = 0; s < 4; s++) {
                uint32_t a[4][4];
                #pragma unroll
                for (int i = 0; i < 4; i++) {
                    int r = wm0 + i * 16 + g;
                    a[i][0] = lds32(sA + off16(r,     s * 32 + 4 * tig));
                    a[i][1] = lds32(sA + off16(r + 8, s * 32 + 4 * tig));
                    a[i][2] = lds32(sA + off16(r,     s * 32 + 16 + 4 * tig));
                    a[i][3] = lds32(sA + off16(r + 8, s * 32 + 16 + 4 * tig));
                }
                #pragma unroll
                for (int j = 0; j < 4; j++) {
                    int n = wn0 + j * 8 + g;
                    uint32_t bh0 = lds32(sBh + off16(n, s * 32 + 4 * tig));
                    uint32_t bh1 = lds32(sBh + off16(n, s * 32 + 16 + 4 * tig));
                    #pragma unroll
                    for (int i = 0; i < 4; i++) mma_f16(acc[i][j], a[i], bh0, bh1);
                    uint32_t bl0 = lds32(sBl + off16(n, s * 32 + 4 * tig));
                    uint32_t bl1 = lds32(sBl + off16(n, s * 32 + 16 + 4 * tig));
                    #pragma unroll
                    for (int i = 0; i < 4; i++) mma_f16(acc[i][j], a[i], bl0, bl1);
                }
            }
        } else {
            const float* fA = (const float*)sA;
            const float* fB = fA + 4096;
            #pragma unroll
            for (int ks = 0; ks < 4; ks++) {
                const int k = ks * 8 + tig;
                uint32_t a[4][4];
                #pragma unroll
                for (int i = 0; i < 4; i++) {
                    int r = wm0 + i * 16 + g;
                    a[i][0] = __float_as_uint(fA[sidx(r,     k)]);
                    a[i][1] = __float_as_uint(fA[sidx(r + 8, k)]);
                    a[i][2] = __float_as_uint(fA[sidx(r,     k + 4)]);
                    a[i][3] = __float_as_uint(fA[sidx(r + 8, k + 4)]);
                }
                #pragma unroll
                for (int j = 0; j < 4; j++) {
                    int n = wn0 + j * 8 + g;
                    uint32_t b0 = __float_as_uint(fB[sidx(n, k)]);
                    uint32_t b1 = __float_as_uint(fB[sidx(n, k + 4)]);
                    #pragma unroll
                    for (int i = 0; i < 4; i++) mma_tf32(acc[i][j], a[i], b0, b1);
                }
            }
        }
    }

    // epilogue
    float lmax = 0.0f;
    const float inv = expm
        ? fmaxf(__int_as_float(g_amax[0]), 1e-8f) * (1.0f / (127.0f * 2048.0f))
        : 1.0f;
    const int ccol0 = expm ? n0 : MHALF + n0;
    #pragma unroll
    for (int i = 0; i < 4; i++) {
        #pragma unroll
        for (int j = 0; j < 4; j++) {
            int r   = row0 + wm0 + i * 16 + g;
            int col = ccol0 + wn0 + j * 8 + tig * 2;
            float v0 = acc[i][j][0] * inv, v1 = acc[i][j][1] * inv;
            float v2 = acc[i][j][2] * inv, v3 = acc[i][j][3] * inv;
            if (expm) {
                lmax = fmaxf(lmax, fmaxf(fmaxf(fabsf(v0), fabsf(v1)),
                                         fmaxf(fabsf(v2), fabsf(v3))));
            } else {
                v0 = to_tf32(v0); v1 = to_tf32(v1);
                v2 = to_tf32(v2); v3 = to_tf32(v3);
            }
            *(float2*)&g_H[(size_t)r * MDIM + col]       = make_float2(v0, v1);
            *(float2*)&g_H[(size_t)(r + 8) * MDIM + col] = make_float2(v2, v3);
        }
    }

    if (expm) {
        float* red = (float*)smem;
        __syncthreads();
        red[tid] = lmax;
        __syncthreads();
        #pragma unroll
        for (int s = 128; s; s >>= 1) {
            if (tid < s) red[tid] = fmaxf(red[tid], red[tid + s]);
            __syncthreads();
        }
        if (tid == 0) atomicMax(&g_amax[1], __float_as_int(red[0]));
    }
}

// ---------------- GEMM2: out = relu(Hq@W2^T + Hc@Wc^T + b) -------------------
// chunks 0..63: bf16 2-term (K64); chunks 64..191: tf32 single (K32)
__global__ void __launch_bounds__(256, 1) gemm2_kernel(float* __restrict__ outp,
                                                       const float* __restrict__ biasp) {
    extern __shared__ char smem[];
    const int tid = threadIdx.x, wid = tid >> 5, lane = tid & 31;
    const int g = lane >> 2, tig = lane & 3;
    const int wm0 = (wid & 1) * 64, wn0 = (wid >> 1) * 32;
    const int n0 = blockIdx.x * 128, row0 = blockIdx.y * 128;
    const uint32_t sbase = smem_u32(smem);
    const int NCH = 64 + 128;

    auto issue = [&](int c) {
        const uint32_t st = sbase + (uint32_t)(c & 3) * STG_BYTES;
        if (c < 64) {
            const int k0 = c * 64;
            const __nv_bfloat16* As = g_Hq16   + (size_t)row0 * MHALF + k0;
            const __nv_bfloat16* Bh = g_W2hi16 + (size_t)n0 * MHALF + k0;
            const __nv_bfloat16* Bl = g_W2lo16 + (size_t)n0 * MHALF + k0;
            #pragma unroll
            for (int p = 0; p < 4; p++) {
                int l = tid + p * 256;
                int r = l >> 3, gc = l & 7;
                uint32_t d = st + (uint32_t)(r * 128 + ((gc ^ (r & 7)) << 4));
                cp16(d,         As + (size_t)r * MHALF + gc * 8);
                cp16(d + 16384, Bh + (size_t)r * MHALF + gc * 8);
                cp16(d + 32768, Bl + (size_t)r * MHALF + gc * 8);
            }
        } else {
            const int k0 = (c - 64) * 32;
            const float* As = g_H  + (size_t)row0 * MDIM + MHALF + k0;
            const float* Bs = g_Wc + (size_t)n0 * MHALF + k0;
            #pragma unroll
            for (int p = 0; p < 4; p++) {
                int l = tid + p * 256;
                int r = l >> 3, gc = l & 7;
                uint32_t d = st + (uint32_t)(r * 128 + ((gc ^ (r & 7)) << 4));
                cp16(d,         As + (size_t)r * MDIM + gc * 4);
                cp16(d + 16384, Bs + (size_t)r * MHALF + gc * 4);
            }
        }
        cp_commit();
    };

    issue(0); issue(1); issue(2);

    float acc[4][4][4] = {};

    for (int c = 0; c < NCH; c++) {
        cp_wait<2>();
        __syncthreads();
        if (c + 3 < NCH) issue(c + 3); else cp_commit();

        const char* sA = smem + (c & 3) * STG_BYTES;
        if (c < 64) {
            const char* sBh = sA + 16384;
            const char* sBl = sA + 32768;
            #pragma unroll
            for (int s = 0; s < 4; s++) {
                uint32_t a[4][4];
                #pragma unroll
                for (int i = 0; i < 4; i++) {
                    int r = wm0 + i * 16 + g;
                    a[i][0] = lds32(sA + off16(r,     s * 32 + 4 * tig));
                    a[i][1] = lds32(sA + off16(r + 8, s * 32 + 4 * tig));
                    a[i][2] = lds32(sA + off16(r,     s * 32 + 16 + 4 * tig));
                    a[i][3] = lds32(sA + off16(r + 8, s * 32 + 16 + 4 * tig));
                }
                #pragma unroll
                for (int j = 0; j < 4; j++) {
                    int n = wn0 + j * 8 + g;
                    uint32_t bh0 = lds32(sBh + off16(n, s * 32 + 4 * tig));
                    uint32_t bh1 = lds32(sBh + off16(n, s * 32 + 16 + 4 * tig));
                    #pragma unroll
                    for (int i = 0; i < 4; i++) mma_bf16(acc[i][j], a[i], bh0, bh1);
                    uint32_t bl0 = lds32(sBl + off16(n, s * 32 + 4 * tig));
                    uint32_t bl1 = lds32(sBl + off16(n, s * 32 + 16 + 4 * tig));
                    #pragma unroll
                    for (int i = 0; i < 4; i++) mma_bf16(acc[i][j], a[i], bl0, bl1);
                }
            }
        } else {
            const float* fA = (const float*)sA;
            const float* fB = fA + 4096;
            #pragma unroll
            for (int ks = 0; ks < 4; ks++) {
                const int k = ks * 8 + tig;
                uint32_t a[4][4];
                #pragma unroll
                for (int i = 0; i < 4; i++) {
                    int r = wm0 + i * 16 + g;
                    a[i][0] = __float_as_uint(fA[sidx(r,     k)]);
                    a[i][1] = __float_as_uint(fA[sidx(r + 8, k)]);
                    a[i][2] = __float_as_uint(fA[sidx(r,     k + 4)]);
                    a[i][3] = __float_as_uint(fA[sidx(r + 8, k + 4)]);
                }
                #pragma unroll
                for (int j = 0; j < 4; j++) {
                    int n = wn0 + j * 8 + g;
                    uint32_t b0 = __float_as_uint(fB[sidx(n, k)]);
                    uint32_t b1 = __float_as_uint(fB[sidx(n, k + 4)]);
                    #pragma unroll
                    for (int i = 0; i < 4; i++) mma_tf32(acc[i][j], a[i], b0, b1);
                }
            }
        }
    }

    #pragma unroll
    for (int i = 0; i < 4; i++) {
        #pragma unroll
        for (int j = 0; j < 4; j++) {
            int r   = row0 + wm0 + i * 16 + g;
            int col = n0 + wn0 + j * 8 + tig * 2;
            float b0 = biasp[col], b1 = biasp[col + 1];
            float v0 = fmaxf(acc[i][j][0] + b0, 0.0f);
            float v1 = fmaxf(acc[i][j][1] + b1, 0.0f);
            float v2 = fmaxf(acc[i][j][2] + b0, 0.0f);
            float v3 = fmaxf(acc[i][j][3] + b1, 0.0f);
            *(float2*)&outp[(size_t)r * NDIM + col]       = make_float2(v0, v1);
            *(float2*)&outp[(size_t)(r + 8) * NDIM + col] = make_float2(v2, v3);
        }
    }
}

// ---------------- launcher ---------------------------------------------------
extern "C" void kernel_launch(void* const* d_in, const int* in_sizes, int n_in,
                              void* d_out, int out_size) {
    const float* x    = (const float*)d_in[0];
    const float* W    = (const float*)d_in[1];
    const float* b    = (const float*)d_in[2];
    const int*   idx  = (const int*)d_in[3];
    const int*   idxc = (const int*)d_in[4];
    float* out = (float*)d_out;

    const int SMEM = NSTG * STG_BYTES;  // 192KB
    cudaFuncSetAttribute(gemm1_kernel, cudaFuncAttributeMaxDynamicSharedMemorySize, SMEM);
    cudaFuncSetAttribute(gemm2_kernel, cudaFuncAttributeMaxDynamicSharedMemorySize, SMEM);

    reset_kernel<<<1, 32>>>();
    quant_w_kernel<<<(NDIM * MHALF / 32) / 8, 256>>>(W, idx);
    gather_wc_kernel<<<NDIM * MHALF / 256, 256>>>(W, idxc);
    transpose_kernel<<<dim3(MHALF / 32, NDIM / 32, 2), dim3(32, 8)>>>();
    absmax_x_kernel<<<1024, 256>>>((const float4*)x);
    quant_x_kernel<<<BATCH * NDIM / 256, 256>>>(x);

    gemm1_kernel<<<dim3(MDIM / 128, BATCH / 128), 256, SMEM>>>();

    scale_w2_kernel<<<NDIM * MHALF / 256, 256>>>();
    quant_h_kernel<<<(BATCH * MHALF / 4) / 256, 256>>>();

    gemm2_kernel<<<dim3(NDIM / 128, BATCH / 128), 256, SMEM>>>(out, b);
}

// round 7
// speedup vs baseline: 6.5313x; 1.6875x over previous
#include <cuda_runtime.h>
#include <cuda_fp16.h>
#include <cuda_bf16.h>
#include <cstdint>

#define BATCH 8192
#define NDIM  1024
#define MDIM  8192
#define MHALF 4096

#define NSTG      4
#define STG_BYTES 49152   // 48KB per stage (big GEMMs)

// ---------------- scratch ----------------------------------------------------
__device__ float         g_Wq     [(size_t)NDIM * MHALF];   // raw quantized weights [n][j]
__device__ __half        g_WqThi16[(size_t)MHALF * NDIM];   // fp16 hi of 2048*Wq, [j][n]
__device__ __half        g_WqTlo16[(size_t)MHALF * NDIM];   // fp16 lo of 2048*Wq, [j][n]
__device__ float         g_Wc     [(size_t)NDIM * MHALF];   // tf32(Wc) [n][j]
__device__ float         g_G      [(size_t)NDIM * NDIM];    // tf32(Wc @ Wc^T)
__device__ __nv_bfloat16 g_W2hi16 [(size_t)NDIM * MHALF];   // bf16 hi of (amax_h/127)*Wq
__device__ __nv_bfloat16 g_W2lo16 [(size_t)NDIM * MHALF];   // bf16 lo
__device__ __half        g_xq16   [(size_t)BATCH * NDIM];   // int-valued quantized x (fp16)
__device__ float         g_xc     [(size_t)BATCH * NDIM];   // tf32(x)
__device__ float         g_H      [(size_t)BATCH * MHALF];  // H_exp raw fp32
__device__ __nv_bfloat16 g_Hq16   [(size_t)BATCH * MHALF];  // int-valued quantized H_exp
__device__ int           g_amax[2];

// ---------------- helpers ----------------------------------------------------
__device__ __forceinline__ float to_tf32(float x) {
    float r; asm("cvt.rna.tf32.f32 %0, %1;" : "=f"(r) : "f"(x)); return r;
}
__device__ __forceinline__ uint32_t smem_u32(const void* p) {
    uint32_t a;
    asm("{ .reg .u64 t; cvta.to.shared.u64 t, %1; cvt.u32.u64 %0, t; }" : "=r"(a) : "l"(p));
    return a;
}
__device__ __forceinline__ void cp16(uint32_t d, const void* s) {
    asm volatile("cp.async.cg.shared.global [%0], [%1], 16;" :: "r"(d), "l"(s));
}
__device__ __forceinline__ void cp_commit() {
    asm volatile("cp.async.commit_group;" ::: "memory");
}
template<int N> __device__ __forceinline__ void cp_wait() {
    asm volatile("cp.async.wait_group %0;" :: "n"(N) : "memory");
}
__device__ __forceinline__ void mma_tf32(float* d, const uint32_t* a, uint32_t b0, uint32_t b1) {
    asm volatile(
        "mma.sync.aligned.m16n8k8.row.col.f32.tf32.tf32.f32 "
        "{%0,%1,%2,%3},{%4,%5,%6,%7},{%8,%9},{%0,%1,%2,%3};"
        : "+f"(d[0]), "+f"(d[1]), "+f"(d[2]), "+f"(d[3])
        : "r"(a[0]), "r"(a[1]), "r"(a[2]), "r"(a[3]), "r"(b0), "r"(b1));
}
__device__ __forceinline__ void mma_f16(float* d, const uint32_t* a, uint32_t b0, uint32_t b1) {
    asm volatile(
        "mma.sync.aligned.m16n8k16.row.col.f32.f16.f16.f32 "
        "{%0,%1,%2,%3},{%4,%5,%6,%7},{%8,%9},{%0,%1,%2,%3};"
        : "+f"(d[0]), "+f"(d[1]), "+f"(d[2]), "+f"(d[3])
        : "r"(a[0]), "r"(a[1]), "r"(a[2]), "r"(a[3]), "r"(b0), "r"(b1));
}
__device__ __forceinline__ void mma_bf16(float* d, const uint32_t* a, uint32_t b0, uint32_t b1) {
    asm volatile(
        "mma.sync.aligned.m16n8k16.row.col.f32.bf16.bf16.f32 "
        "{%0,%1,%2,%3},{%4,%5,%6,%7},{%8,%9},{%0,%1,%2,%3};"
        : "+f"(d[0]), "+f"(d[1]), "+f"(d[2]), "+f"(d[3])
        : "r"(a[0]), "r"(a[1]), "r"(a[2]), "r"(a[3]), "r"(b0), "r"(b1));
}
// tf32 tile word index: [rows][32 floats], 16B-granule xor swizzle
__device__ __forceinline__ int sidx(int r, int k) {
    return r * 32 + (((k >> 2) ^ (r & 7)) << 2) + (k & 3);
}
// 16-bit tile byte offset: [rows][128B = 64 halves], granule swizzle. kb = byte col
__device__ __forceinline__ int off16(int r, int kb) {
    return r * 128 + ((((kb >> 4) ^ (r & 7)) << 4) | (kb & 15));
}
__device__ __forceinline__ uint32_t lds32(const char* p) {
    return *(const uint32_t*)p;
}

// ---------------- prep kernels ----------------------------------------------
__global__ void reset_kernel() { g_amax[0] = 0; g_amax[1] = 0; }

__global__ void quant_w_kernel(const float* __restrict__ W, const int* __restrict__ idx) {
    int gw   = (blockIdx.x * blockDim.x + threadIdx.x) >> 5;
    int lane = threadIdx.x & 31;
    if (gw >= (NDIM * MHALF) / 32) return;
    int flat = gw * 32 + lane;
    int n = flat >> 12;
    int j = flat & (MHALF - 1);
    float w = W[(size_t)n * MDIM + idx[j]];

    float s = fabsf(w);
    #pragma unroll
    for (int o = 16; o; o >>= 1) s = fmaxf(s, __shfl_xor_sync(0xffffffffu, s, o));
    s = fmaxf(s, 1e-8f);

    float nb  = w / s;
    float anb = fabsf(nb);

    float v1 = anb; int i1 = lane;
    #pragma unroll
    for (int o = 16; o; o >>= 1) {
        float ov = __shfl_xor_sync(0xffffffffu, v1, o);
        int   oi = __shfl_xor_sync(0xffffffffu, i1, o);
        if (ov > v1 || (ov == v1 && oi < i1)) { v1 = ov; i1 = oi; }
    }
    float m2 = (lane == i1) ? -1.0f : anb;
    float v2 = m2; int i2 = lane;
    #pragma unroll
    for (int o = 16; o; o >>= 1) {
        float ov = __shfl_xor_sync(0xffffffffu, v2, o);
        int   oi = __shfl_xor_sync(0xffffffffu, i2, o);
        if (ov > v2 || (ov == v2 && oi < i2)) { v2 = ov; i2 = oi; }
    }
    bool top = (lane == i1) || (lane == i2);

    float q4  = rintf(nb * 7.0f) / 7.0f;
    float sgn = (nb > 0.0f) ? 1.0f : ((nb < 0.0f) ? -1.0f : 0.0f);
    float q2  = sgn * ((anb > 0.66f) ? 1.0f : (1.0f / 3.0f));
    g_Wq[flat] = (top ? q4 : q2) * s;
}

__global__ void gather_wc_kernel(const float* __restrict__ W, const int* __restrict__ idxc) {
    int t = blockIdx.x * blockDim.x + threadIdx.x;
    if (t >= NDIM * MHALF) return;
    int n = t >> 12;
    int j = t & (MHALF - 1);
    g_Wc[t] = to_tf32(W[(size_t)n * MDIM + idxc[j]]);
}

// transpose g_Wq [NDIM][MHALF] -> fp16 hi/lo of 2048*Wq in [MHALF][NDIM]
__global__ void transpose_kernel() {
    __shared__ float t[32][33];
    int j0 = blockIdx.x * 32, n0 = blockIdx.y * 32;
    int tx = threadIdx.x, ty = threadIdx.y;
    #pragma unroll
    for (int s = 0; s < 32; s += 8)
        t[ty + s][tx] = g_Wq[(size_t)(n0 + ty + s) * MHALF + j0 + tx];
    __syncthreads();
    #pragma unroll
    for (int s = 0; s < 32; s += 8) {
        float v = t[tx][ty + s] * 2048.0f;
        __half h = __float2half_rn(v);
        __half l = __float2half_rn(v - __half2float(h));
        size_t o = (size_t)(j0 + ty + s) * NDIM + n0 + tx;
        g_WqThi16[o] = h;
        g_WqTlo16[o] = l;
    }
}

__global__ void absmax_x_kernel(const float4* __restrict__ x4) {
    __shared__ float sm[256];
    const long n4 = (long)BATCH * NDIM / 4;
    float m = 0.0f;
    for (long i = (long)blockIdx.x * blockDim.x + threadIdx.x; i < n4;
         i += (long)gridDim.x * blockDim.x) {
        float4 v = x4[i];
        m = fmaxf(m, fmaxf(fmaxf(fabsf(v.x), fabsf(v.y)), fmaxf(fabsf(v.z), fabsf(v.w))));
    }
    sm[threadIdx.x] = m;
    __syncthreads();
    #pragma unroll
    for (int s = 128; s; s >>= 1) {
        if (threadIdx.x < s) sm[threadIdx.x] = fmaxf(sm[threadIdx.x], sm[threadIdx.x + s]);
        __syncthreads();
    }
    if (threadIdx.x == 0) atomicMax(&g_amax[0], __float_as_int(sm[0]));
}

__global__ void quant_x_kernel(const float* __restrict__ x) {
    int i = blockIdx.x * blockDim.x + threadIdx.x;
    if (i >= BATCH * NDIM) return;
    float sc = 127.0f / fmaxf(__int_as_float(g_amax[0]), 1e-8f);
    float v = x[i];
    g_xq16[i] = __float2half_rn(fminf(fmaxf(rintf(v * sc), -128.0f), 127.0f));
    g_xc[i]   = to_tf32(v);
}

// W2hi/lo (bf16) = split( (amax_h/127) * Wq )
__global__ void scale_w2_kernel() {
    int i = blockIdx.x * blockDim.x + threadIdx.x;
    if (i >= NDIM * MHALF) return;
    float f = fmaxf(__int_as_float(g_amax[1]), 1e-8f) * (1.0f / 127.0f);
    float v = g_Wq[i] * f;
    __nv_bfloat16 h = __float2bfloat16_rn(v);
    g_W2hi16[i] = h;
    g_W2lo16[i] = __float2bfloat16_rn(v - __bfloat162float(h));
}

// quantize H_exp -> integer-valued bf16
__global__ void quant_h_kernel() {
    int t = blockIdx.x * blockDim.x + threadIdx.x;
    if (t >= BATCH * MHALF / 4) return;
    int c4 = t * 4;
    float sh = 127.0f / fmaxf(__int_as_float(g_amax[1]), 1e-8f);
    float4 v = *(const float4*)&g_H[c4];
    __nv_bfloat16 o[4];
    o[0] = __float2bfloat16_rn(fminf(fmaxf(rintf(v.x * sh), -128.0f), 127.0f));
    o[1] = __float2bfloat16_rn(fminf(fmaxf(rintf(v.y * sh), -128.0f), 127.0f));
    o[2] = __float2bfloat16_rn(fminf(fmaxf(rintf(v.z * sh), -128.0f), 127.0f));
    o[3] = __float2bfloat16_rn(fminf(fmaxf(rintf(v.w * sh), -128.0f), 127.0f));
    *(uint2*)&g_Hq16[c4] = *(uint2*)o;
}

// ---------------- SYRK: G = Wc @ Wc^T (tf32), 64x64 tiles -------------------
__global__ void __launch_bounds__(128, 2) syrk_kernel() {
    extern __shared__ char smem[];   // 4 stages x 16KB
    const int tid = threadIdx.x, wid = tid >> 5, lane = tid & 31;
    const int g = lane >> 2, tig = lane & 3;
    const int wm0 = (wid & 1) * 32, wn0 = (wid >> 1) * 32;
    const int m0 = blockIdx.y * 64, n0 = blockIdx.x * 64;
    const uint32_t sbase = smem_u32(smem);
    const int NCH = MHALF / 32;

    auto issue = [&](int c) {
        const int k0 = c * 32;
        const uint32_t st = sbase + (uint32_t)(c & 3) * 16384;
        const float* As = g_Wc + (size_t)m0 * MHALF + k0;
        const float* Bs = g_Wc + (size_t)n0 * MHALF + k0;
        #pragma unroll
        for (int p = 0; p < 4; p++) {
            int l = tid + p * 128;
            int r = l >> 3, gc = l & 7;
            uint32_t d = st + (uint32_t)(r * 32 + ((gc ^ (r & 7)) << 2)) * 4;
            cp16(d,        As + (size_t)r * MHALF + gc * 4);
            cp16(d + 8192, Bs + (size_t)r * MHALF + gc * 4);
        }
        cp_commit();
    };
    issue(0); issue(1); issue(2);

    float acc[2][4][4] = {};
    for (int c = 0; c < NCH; c++) {
        cp_wait<2>();
        __syncthreads();
        if (c + 3 < NCH) issue(c + 3); else cp_commit();
        const float* fA = (const float*)(smem + (c & 3) * 16384);
        const float* fB = fA + 2048;
        #pragma unroll
        for (int ks = 0; ks < 4; ks++) {
            const int k = ks * 8 + tig;
            uint32_t a[2][4];
            #pragma unroll
            for (int i = 0; i < 2; i++) {
                int r = wm0 + i * 16 + g;
                a[i][0] = __float_as_uint(fA[sidx(r,     k)]);
                a[i][1] = __float_as_uint(fA[sidx(r + 8, k)]);
                a[i][2] = __float_as_uint(fA[sidx(r,     k + 4)]);
                a[i][3] = __float_as_uint(fA[sidx(r + 8, k + 4)]);
            }
            #pragma unroll
            for (int j = 0; j < 4; j++) {
                int n = wn0 + j * 8 + g;
                uint32_t b0 = __float_as_uint(fB[sidx(n, k)]);
                uint32_t b1 = __float_as_uint(fB[sidx(n, k + 4)]);
                #pragma unroll
                for (int i = 0; i < 2; i++) mma_tf32(acc[i][j], a[i], b0, b1);
            }
        }
    }
    #pragma unroll
    for (int i = 0; i < 2; i++)
        #pragma unroll
        for (int j = 0; j < 4; j++) {
            int r   = m0 + wm0 + i * 16 + g;
            int col = n0 + wn0 + j * 8 + tig * 2;
            float v0 = to_tf32(acc[i][j][0]), v1 = to_tf32(acc[i][j][1]);
            float v2 = to_tf32(acc[i][j][2]), v3 = to_tf32(acc[i][j][3]);
            *(float2*)&g_G[(size_t)r * NDIM + col]       = make_float2(v0, v1);
            *(float2*)&g_G[(size_t)(r + 8) * NDIM + col] = make_float2(v2, v3);
        }
}

// ---------------- GEMM1: H_exp = xq @ Wq (fp16 2-term split) -----------------
__global__ void __launch_bounds__(256, 1) gemm1_kernel() {
    extern __shared__ char smem[];
    const int tid = threadIdx.x, wid = tid >> 5, lane = tid & 31;
    const int g = lane >> 2, tig = lane & 3;
    const int wm0 = (wid & 1) * 64, wn0 = (wid >> 1) * 32;
    const int n0 = blockIdx.x * 128, row0 = blockIdx.y * 128;
    const uint32_t sbase = smem_u32(smem);
    const int NCH = NDIM / 64;

    auto issue = [&](int c) {
        const int k0 = c * 64;
        const uint32_t st = sbase + (uint32_t)(c & 3) * STG_BYTES;
        const __half* As = g_xq16    + (size_t)row0 * NDIM + k0;
        const __half* Bh = g_WqThi16 + (size_t)n0 * NDIM + k0;
        const __half* Bl = g_WqTlo16 + (size_t)n0 * NDIM + k0;
        #pragma unroll
        for (int p = 0; p < 4; p++) {
            int l = tid + p * 256;
            int r = l >> 3, gc = l & 7;
            uint32_t d = st + (uint32_t)(r * 128 + ((gc ^ (r & 7)) << 4));
            cp16(d,         As + (size_t)r * NDIM + gc * 8);
            cp16(d + 16384, Bh + (size_t)r * NDIM + gc * 8);
            cp16(d + 32768, Bl + (size_t)r * NDIM + gc * 8);
        }
        cp_commit();
    };

    issue(0); issue(1); issue(2);

    float acc[4][4][4] = {};

    for (int c = 0; c < NCH; c++) {
        cp_wait<2>();
        __syncthreads();
        if (c + 3 < NCH) issue(c + 3); else cp_commit();

        const char* sA  = smem + (c & 3) * STG_BYTES;
        const char* sBh = sA + 16384;
        const char* sBl = sA + 32768;
        #pragma unroll
        for (int s = 0; s < 4; s++) {
            uint32_t a[4][4];
            #pragma unroll
            for (int i = 0; i < 4; i++) {
                int r = wm0 + i * 16 + g;
                a[i][0] = lds32(sA + off16(r,     s * 32 + 4 * tig));
                a[i][1] = lds32(sA + off16(r + 8, s * 32 + 4 * tig));
                a[i][2] = lds32(sA + off16(r,     s * 32 + 16 + 4 * tig));
                a[i][3] = lds32(sA + off16(r + 8, s * 32 + 16 + 4 * tig));
            }
            #pragma unroll
            for (int j = 0; j < 4; j++) {
                int n = wn0 + j * 8 + g;
                uint32_t bh0 = lds32(sBh + off16(n, s * 32 + 4 * tig));
                uint32_t bh1 = lds32(sBh + off16(n, s * 32 + 16 + 4 * tig));
                #pragma unroll
                for (int i = 0; i < 4; i++) mma_f16(acc[i][j], a[i], bh0, bh1);
                uint32_t bl0 = lds32(sBl + off16(n, s * 32 + 4 * tig));
                uint32_t bl1 = lds32(sBl + off16(n, s * 32 + 16 + 4 * tig));
                #pragma unroll
                for (int i = 0; i < 4; i++) mma_f16(acc[i][j], a[i], bl0, bl1);
            }
        }
    }

    float lmax = 0.0f;
    const float inv = fmaxf(__int_as_float(g_amax[0]), 1e-8f) * (1.0f / (127.0f * 2048.0f));
    #pragma unroll
    for (int i = 0; i < 4; i++) {
        #pragma unroll
        for (int j = 0; j < 4; j++) {
            int r   = row0 + wm0 + i * 16 + g;
            int col = n0 + wn0 + j * 8 + tig * 2;
            float v0 = acc[i][j][0] * inv, v1 = acc[i][j][1] * inv;
            float v2 = acc[i][j][2] * inv, v3 = acc[i][j][3] * inv;
            lmax = fmaxf(lmax, fmaxf(fmaxf(fabsf(v0), fabsf(v1)),
                                     fmaxf(fabsf(v2), fabsf(v3))));
            *(float2*)&g_H[(size_t)r * MHALF + col]       = make_float2(v0, v1);
            *(float2*)&g_H[(size_t)(r + 8) * MHALF + col] = make_float2(v2, v3);
        }
    }

    float* red = (float*)smem;
    __syncthreads();
    red[tid] = lmax;
    __syncthreads();
    #pragma unroll
    for (int s = 128; s; s >>= 1) {
        if (tid < s) red[tid] = fmaxf(red[tid], red[tid + s]);
        __syncthreads();
    }
    if (tid == 0) atomicMax(&g_amax[1], __float_as_int(red[0]));
}

// ---------------- GEMM2: out = relu(Hq@W2^T + x@G + b) -----------------------
// chunks 0..63: bf16 2-term (K64 over MHALF); chunks 64..95: tf32 (K32 over NDIM)
__global__ void __launch_bounds__(256, 1) gemm2_kernel(float* __restrict__ outp,
                                                       const float* __restrict__ biasp) {
    extern __shared__ char smem[];
    const int tid = threadIdx.x, wid = tid >> 5, lane = tid & 31;
    const int g = lane >> 2, tig = lane & 3;
    const int wm0 = (wid & 1) * 64, wn0 = (wid >> 1) * 32;
    const int n0 = blockIdx.x * 128, row0 = blockIdx.y * 128;
    const uint32_t sbase = smem_u32(smem);
    const int NCH = 64 + NDIM / 32;   // 96

    auto issue = [&](int c) {
        const uint32_t st = sbase + (uint32_t)(c & 3) * STG_BYTES;
        if (c < 64) {
            const int k0 = c * 64;
            const __nv_bfloat16* As = g_Hq16   + (size_t)row0 * MHALF + k0;
            const __nv_bfloat16* Bh = g_W2hi16 + (size_t)n0 * MHALF + k0;
            const __nv_bfloat16* Bl = g_W2lo16 + (size_t)n0 * MHALF + k0;
            #pragma unroll
            for (int p = 0; p < 4; p++) {
                int l = tid + p * 256;
                int r = l >> 3, gc = l & 7;
                uint32_t d = st + (uint32_t)(r * 128 + ((gc ^ (r & 7)) << 4));
                cp16(d,         As + (size_t)r * MHALF + gc * 8);
                cp16(d + 16384, Bh + (size_t)r * MHALF + gc * 8);
                cp16(d + 32768, Bl + (size_t)r * MHALF + gc * 8);
            }
        } else {
            const int k0 = (c - 64) * 32;
            const float* As = g_xc + (size_t)row0 * NDIM + k0;
            const float* Bs = g_G  + (size_t)n0 * NDIM + k0;
            #pragma unroll
            for (int p = 0; p < 4; p++) {
                int l = tid + p * 256;
                int r = l >> 3, gc = l & 7;
                uint32_t d = st + (uint32_t)(r * 128 + ((gc ^ (r & 7)) << 4));
                cp16(d,         As + (size_t)r * NDIM + gc * 4);
                cp16(d + 16384, Bs + (size_t)r * NDIM + gc * 4);
            }
        }
        cp_commit();
    };

    issue(0); issue(1); issue(2);

    float acc[4][4][4] = {};

    for (int c = 0; c < NCH; c++) {
        cp_wait<2>();
        __syncthreads();
        if (c + 3 < NCH) issue(c + 3); else cp_commit();

        const char* sA = smem + (c & 3) * STG_BYTES;
        if (c < 64) {
            const char* sBh = sA + 16384;
            const char* sBl = sA + 32768;
            #pragma unroll
            for (int s = 0; s < 4; s++) {
                uint32_t a[4][4];
                #pragma unroll
                for (int i = 0; i < 4; i++) {
                    int r = wm0 + i * 16 + g;
                    a[i][0] = lds32(sA + off16(r,     s * 32 + 4 * tig));
                    a[i][1] = lds32(sA + off16(r + 8, s * 32 + 4 * tig));
                    a[i][2] = lds32(sA + off16(r,     s * 32 + 16 + 4 * tig));
                    a[i][3] = lds32(sA + off16(r + 8, s * 32 + 16 + 4 * tig));
                }
                #pragma unroll
                for (int j = 0; j < 4; j++) {
                    int n = wn0 + j * 8 + g;
                    uint32_t bh0 = lds32(sBh + off16(n, s * 32 + 4 * tig));
                    uint32_t bh1 = lds32(sBh + off16(n, s * 32 + 16 + 4 * tig));
                    #pragma unroll
                    for (int i = 0; i < 4; i++) mma_bf16(acc[i][j], a[i], bh0, bh1);
                    uint32_t bl0 = lds32(sBl + off16(n, s * 32 + 4 * tig));
                    uint32_t bl1 = lds32(sBl + off16(n, s * 32 + 16 + 4 * tig));
                    #pragma unroll
                    for (int i = 0; i < 4; i++) mma_bf16(acc[i][j], a[i], bl0, bl1);
                }
            }
        } else {
            const float* fA = (const float*)sA;
            const float* fB = fA + 4096;
            #pragma unroll
            for (int ks = 0; ks < 4; ks++) {
                const int k = ks * 8 + tig;
                uint32_t a[4][4];
                #pragma unroll
                for (int i = 0; i < 4; i++) {
                    int r = wm0 + i * 16 + g;
                    a[i][0] = __float_as_uint(fA[sidx(r,     k)]);
                    a[i][1] = __float_as_uint(fA[sidx(r + 8, k)]);
                    a[i][2] = __float_as_uint(fA[sidx(r,     k + 4)]);
                    a[i][3] = __float_as_uint(fA[sidx(r + 8, k + 4)]);
                }
                #pragma unroll
                for (int j = 0; j < 4; j++) {
                    int n = wn0 + j * 8 + g;
                    uint32_t b0 = __float_as_uint(fB[sidx(n, k)]);
                    uint32_t b1 = __float_as_uint(fB[sidx(n, k + 4)]);
                    #pragma unroll
                    for (int i = 0; i < 4; i++) mma_tf32(acc[i][j], a[i], b0, b1);
                }
            }
        }
    }

    #pragma unroll
    for (int i = 0; i < 4; i++) {
        #pragma unroll
        for (int j = 0; j < 4; j++) {
            int r   = row0 + wm0 + i * 16 + g;
            int col = n0 + wn0 + j * 8 + tig * 2;
            float b0 = biasp[col], b1 = biasp[col + 1];
            float v0 = fmaxf(acc[i][j][0] + b0, 0.0f);
            float v1 = fmaxf(acc[i][j][1] + b1, 0.0f);
            float v2 = fmaxf(acc[i][j][2] + b0, 0.0f);
            float v3 = fmaxf(acc[i][j][3] + b1, 0.0f);
            *(float2*)&outp[(size_t)r * NDIM + col]       = make_float2(v0, v1);
            *(float2*)&outp[(size_t)(r + 8) * NDIM + col] = make_float2(v2, v3);
        }
    }
}

// ---------------- launcher ---------------------------------------------------
extern "C" void kernel_launch(void* const* d_in, const int* in_sizes, int n_in,
                              void* d_out, int out_size) {
    const float* x    = (const float*)d_in[0];
    const float* W    = (const float*)d_in[1];
    const float* b    = (const float*)d_in[2];
    const int*   idx  = (const int*)d_in[3];
    const int*   idxc = (const int*)d_in[4];
    float* out = (float*)d_out;

    const int SMEM = NSTG * STG_BYTES;  // 192KB
    cudaFuncSetAttribute(gemm1_kernel, cudaFuncAttributeMaxDynamicSharedMemorySize, SMEM);
    cudaFuncSetAttribute(gemm2_kernel, cudaFuncAttributeMaxDynamicSharedMemorySize, SMEM);
    cudaFuncSetAttribute(syrk_kernel,  cudaFuncAttributeMaxDynamicSharedMemorySize, 65536);

    reset_kernel<<<1, 32>>>();
    quant_w_kernel<<<(NDIM * MHALF / 32) / 8, 256>>>(W, idx);
    gather_wc_kernel<<<NDIM * MHALF / 256, 256>>>(W, idxc);
    transpose_kernel<<<dim3(MHALF / 32, NDIM / 32), dim3(32, 8)>>>();
    absmax_x_kernel<<<1024, 256>>>((const float4*)x);
    quant_x_kernel<<<BATCH * NDIM / 256, 256>>>(x);

    syrk_kernel<<<dim3(NDIM / 64, NDIM / 64), 128, 65536>>>();
    gemm1_kernel<<<dim3(MHALF / 128, BATCH / 128), 256, SMEM>>>();

    scale_w2_kernel<<<NDIM * MHALF / 256, 256>>>();
    quant_h_kernel<<<(BATCH * MHALF / 4) / 256, 256>>>();

    gemm2_kernel<<<dim3(NDIM / 128, BATCH / 128), 256, SMEM>>>(out, b);
}